// round 10
// baseline (speedup 1.0000x reference)
#include <cuda_runtime.h>
#include <cuda_fp16.h>

#define G      8
#define NNODE  64
#define FPN    8
#define H      128
#define MODES  8
#define BT     16384
#define NT     512

typedef unsigned long long u64;

__device__ __align__(16) __half g_w0h[MODES * H * H];  // [k][i][j] fp16
__device__ __align__(16) __half g_w2h[MODES * H * H];
__device__ __align__(16) __half g_Wa1h[H * H];         // Ws1 - invd*Wn1
__device__ __align__(16) __half g_Wb1h[H * H];         // invd*Wn1
__device__ __align__(16) __half g_Wa3h[H * H];
__device__ __align__(16) __half g_Wb3h[H * H];
__device__ float g_s[MODES];
__device__ float g_invd;

__device__ __forceinline__ u64 pks(float a) {
    u64 r; asm("mov.b64 %0,{%1,%1};" : "=l"(r) : "f"(a)); return r;
}
__device__ __forceinline__ u64 pk2(float a, float b) {
    u64 r; asm("mov.b64 %0,{%1,%2};" : "=l"(r) : "f"(a), "f"(b)); return r;
}
__device__ __forceinline__ void fma2(u64& d, u64 a, u64 b) {
    asm("fma.rn.f32x2 %0,%1,%2,%0;" : "+l"(d) : "l"(a), "l"(b));
}
__device__ __forceinline__ void add2(u64& d, u64 a) {
    asm("add.rn.f32x2 %0,%0,%1;" : "+l"(d) : "l"(a));
}
__device__ __forceinline__ float2 up2(u64 a) {
    float2 r; asm("mov.b64 {%0,%1},%2;" : "=f"(r.x), "=f"(r.y) : "l"(a)); return r;
}
__device__ __forceinline__ void fma4(float4& a, float s, const float4 b) {
    a.x = fmaf(s, b.x, a.x); a.y = fmaf(s, b.y, a.y);
    a.z = fmaf(s, b.z, a.z); a.w = fmaf(s, b.w, a.w);
}
__device__ __forceinline__ u64 ldw(const __half* p) {
    __half2 h = *(const __half2*)p;
    float2 f = __half22float2(h);
    return pk2(f.x, f.y);
}

// Hierarchically reduce 8 floats (4 u64 pairs) across the warp.
__device__ __forceinline__ u64 hred8(u64 r0, u64 r1, u64 r2, u64 r3, int lane) {
    u64 t0 = __shfl_xor_sync(0xffffffffu, r0, 16);
    u64 t1 = __shfl_xor_sync(0xffffffffu, r1, 16);
    u64 t2 = __shfl_xor_sync(0xffffffffu, r2, 16);
    u64 t3 = __shfl_xor_sync(0xffffffffu, r3, 16);
    u64 a0, a1;
    if (lane < 16) { a0 = r0; add2(a0, t0); a1 = r1; add2(a1, t1); }
    else           { a0 = r2; add2(a0, t2); a1 = r3; add2(a1, t3); }
    u64 s0 = __shfl_xor_sync(0xffffffffu, a0, 8);
    u64 s1 = __shfl_xor_sync(0xffffffffu, a1, 8);
    u64 b;
    if ((lane & 8) == 0) { b = a0; add2(b, s0); }
    else                 { b = a1; add2(b, s1); }
    u64 c;
    c = __shfl_xor_sync(0xffffffffu, b, 4); add2(b, c);
    c = __shfl_xor_sync(0xffffffffu, b, 2); add2(b, c);
    c = __shfl_xor_sync(0xffffffffu, b, 1); add2(b, c);
    return b;
}

struct Smem {
    float A[G][MODES][H];
    float B[G][MODES][H];
    float P[G][MODES][H];
    float vbar[G][H];
    float qbar[G][H];
    float sX[G * NNODE * FPN];
    float sXS[G][MODES][FPN];
    float sU8[NNODE][MODES];
    float sWp[FPN * H];
    float sWo[H * FPN];
    float bp[H];
    float b1[H]; float gm1[H]; float be1[H];
    float b3[H]; float gm3[H]; float be3[H];
    float ss[MODES]; float sbo[FPN];
};

// ---------------- prep ----------------
__global__ void prep_all(const float* __restrict__ w0, const float* __restrict__ w2,
                         const float* __restrict__ adj, const float* __restrict__ Uin,
                         const float* __restrict__ Ws1, const float* __restrict__ Wn1,
                         const float* __restrict__ Ws3, const float* __restrict__ Wn3) {
    const float invd = adj[1];
    const int total = MODES * H * H;
    for (int o = blockIdx.x * blockDim.x + threadIdx.x; o < total;
         o += gridDim.x * blockDim.x) {
        int k = o >> 14, rem = o & 16383, i = rem >> 7, j = rem & 127;
        int src = ((i << 7) + j) * MODES + k;
        g_w0h[o] = __float2half(w0[src]);
        g_w2h[o] = __float2half(w2[src]);
    }
    for (int o = blockIdx.x * blockDim.x + threadIdx.x; o < H * H;
         o += gridDim.x * blockDim.x) {
        float wn1 = Wn1[o], wn3 = Wn3[o];
        g_Wa1h[o] = __float2half(Ws1[o] - invd * wn1);
        g_Wb1h[o] = __float2half(invd * wn1);
        g_Wa3h[o] = __float2half(Ws3[o] - invd * wn3);
        g_Wb3h[o] = __float2half(invd * wn3);
    }
    if (blockIdx.x == 0 && threadIdx.x < MODES) {
        int k = threadIdx.x;
        float s = 0.f;
        for (int m = 0; m < NNODE; m++) s += Uin[m * NNODE + k];
        g_s[k] = s;
        if (k == 0) g_invd = invd;
    }
}

// ---------------- stages (16 warps) ----------------
__device__ __forceinline__ void mode_mix(const float (*xf)[MODES][H],
                                         float (*of)[MODES][H],
                                         const __half* __restrict__ wt,
                                         int warp, int lane) {
    const int k = warp >> 1;
    const int j2 = (warp & 1) * 64 + lane * 2;
    const __half* wk = wt + k * (H * H) + j2;
    u64 acc[G];
#pragma unroll
    for (int g = 0; g < G; g++) acc[g] = 0ull;
#pragma unroll 4
    for (int i4 = 0; i4 < H / 4; i4++) {
        float4 xv[G];
#pragma unroll
        for (int g = 0; g < G; g++) xv[g] = *(const float4*)&xf[g][k][i4 * 4];
        u64 w[4];
#pragma unroll
        for (int ii = 0; ii < 4; ii++) w[ii] = ldw(wk + (i4 * 4 + ii) * H);
#pragma unroll
        for (int ii = 0; ii < 4; ii++)
#pragma unroll
            for (int g = 0; g < G; g++) fma2(acc[g], pks((&xv[g].x)[ii]), w[ii]);
    }
#pragma unroll
    for (int g = 0; g < G; g++) *(u64*)&of[g][k][j2] = acc[g];
}

__device__ void pq_gemm(Smem& S, const __half* __restrict__ Wa,
                        const __half* __restrict__ Wb, int warp, int lane) {
    const int g = warp >> 1;
    const int j2 = (warp & 1) * 64 + lane * 2;
    const __half* __restrict__ wa = Wa + j2;
    const __half* __restrict__ wb = Wb + j2;
    u64 acc[MODES];
    u64 accq = 0ull;
#pragma unroll
    for (int k = 0; k < MODES; k++) acc[k] = 0ull;
#pragma unroll 2
    for (int i4 = 0; i4 < H / 4; i4++) {
        float4 ov[MODES];
#pragma unroll
        for (int k = 0; k < MODES; k++)
            ov[k] = *(const float4*)&S.B[g][k][i4 * 4];
        float4 vv = *(const float4*)&S.vbar[g][i4 * 4];
        u64 wav[4], wbv[4];
#pragma unroll
        for (int ii = 0; ii < 4; ii++) {
            wav[ii] = ldw(wa + (i4 * 4 + ii) * H);
            wbv[ii] = ldw(wb + (i4 * 4 + ii) * H);
        }
#pragma unroll
        for (int ii = 0; ii < 4; ii++) {
#pragma unroll
            for (int k = 0; k < MODES; k++)
                fma2(acc[k], pks((&ov[k].x)[ii]), wav[ii]);
            fma2(accq, pks((&vv.x)[ii]), wbv[ii]);
        }
    }
#pragma unroll
    for (int k = 0; k < MODES; k++) *(u64*)&S.P[g][k][j2] = acc[k];
    *(u64*)&S.qbar[g][j2] = accq;
}

template <bool FINAL>
__device__ void expand(Smem& S, const float* __restrict__ bsum,
                       const float* __restrict__ gam, const float* __restrict__ bet,
                       float* __restrict__ outg, int warp, int lane) {
    const int g = warp >> 1;
    const int nh = warp & 1;
    const int jc = lane * 4;
    u64 pp0[MODES], pp1[MODES], c0[MODES], c1[MODES];
#pragma unroll
    for (int k = 0; k < MODES; k++) {
        ulonglong2 tp = *(const ulonglong2*)&S.P[g][k][jc];
        pp0[k] = tp.x; pp1[k] = tp.y;
        c0[k] = 0ull; c1[k] = 0ull;
    }
    const ulonglong2 bv = *(const ulonglong2*)&bsum[jc];
    const ulonglong2 qv = *(const ulonglong2*)&S.qbar[g][jc];
    u64 vb0 = bv.x; add2(vb0, qv.x);
    u64 vb1 = bv.y; add2(vb1, qv.y);

    float mb;
    {
        float2 e0 = up2(vb0), e1 = up2(vb1);
        mb = e0.x + e0.y + e1.x + e1.y;
#pragma unroll
        for (int off = 16; off > 0; off >>= 1)
            mb += __shfl_xor_sync(0xffffffffu, mb, off);
    }
    float SPf[8];
    {
        float spl[8];
#pragma unroll
        for (int k = 0; k < MODES; k++) {
            float2 e0 = up2(pp0[k]), e1 = up2(pp1[k]);
            spl[k] = e0.x + e0.y + e1.x + e1.y;
        }
        u64 red = hred8(pk2(spl[0], spl[1]), pk2(spl[2], spl[3]),
                        pk2(spl[4], spl[5]), pk2(spl[6], spl[7]), lane);
        float2 p01 = up2(__shfl_sync(0xffffffffu, red, 0));
        float2 p23 = up2(__shfl_sync(0xffffffffu, red, 8));
        float2 p45 = up2(__shfl_sync(0xffffffffu, red, 16));
        float2 p67 = up2(__shfl_sync(0xffffffffu, red, 24));
        SPf[0] = p01.x; SPf[1] = p01.y; SPf[2] = p23.x; SPf[3] = p23.y;
        SPf[4] = p45.x; SPf[5] = p45.y; SPf[6] = p67.x; SPf[7] = p67.y;
    }

    const float4 gv  = *(const float4*)&gam[jc];
    const float4 bev = *(const float4*)&bet[jc];
    u64 wo[4][4];
    u64 bop = 0ull;
    if (FINAL) {
#pragma unroll
        for (int c = 0; c < 4; c++) {
            ulonglong2 lo = *(const ulonglong2*)&S.sWo[(jc + c) * FPN];
            ulonglong2 hi = *(const ulonglong2*)&S.sWo[(jc + c) * FPN + 4];
            wo[c][0] = lo.x; wo[c][1] = lo.y; wo[c][2] = hi.x; wo[c][3] = hi.y;
        }
        bop = *(const u64*)&S.sbo[(lane >> 3) * 2];
    }
    const int n0 = nh * 32;
    // unroll 2: two independent SHFL/FMA chains in flight per warp
#pragma unroll 2
    for (int n = n0; n < n0 + 32; n++) {
        float4 u0 = *(const float4*)&S.sU8[n][0];
        float4 u1 = *(const float4*)&S.sU8[n][4];
        u64 up[MODES];
        up[0] = pks(u0.x); up[1] = pks(u0.y); up[2] = pks(u0.z); up[3] = pks(u0.w);
        up[4] = pks(u1.x); up[5] = pks(u1.y); up[6] = pks(u1.z); up[7] = pks(u1.w);
        // split accumulation chains (depth 8 -> 4)
        u64 v0 = vb0, v1 = vb1, w0a = 0ull, w1a = 0ull;
#pragma unroll
        for (int k = 0; k < MODES; k += 2) {
            fma2(v0, up[k], pp0[k]);     fma2(v1, up[k], pp1[k]);
            fma2(w0a, up[k + 1], pp0[k + 1]); fma2(w1a, up[k + 1], pp1[k + 1]);
        }
        add2(v0, w0a); add2(v1, w1a);
        float2 va = up2(v0), vb2 = up2(v1);
        float smv = mb;
        smv = fmaf(u0.x, SPf[0], smv); smv = fmaf(u0.y, SPf[1], smv);
        smv = fmaf(u0.z, SPf[2], smv); smv = fmaf(u0.w, SPf[3], smv);
        smv = fmaf(u1.x, SPf[4], smv); smv = fmaf(u1.y, SPf[5], smv);
        smv = fmaf(u1.z, SPf[6], smv); smv = fmaf(u1.w, SPf[7], smv);
        float sq = va.x * va.x + va.y * va.y + vb2.x * vb2.x + vb2.y * vb2.y;
#pragma unroll
        for (int off = 16; off > 0; off >>= 1)
            sq += __shfl_xor_sync(0xffffffffu, sq, off);
        const float mu  = smv * (1.0f / H);
        const float var = sq * (1.0f / H) - mu * mu;
        const float rs  = rsqrtf(var + 1e-5f);
        float hx = fmaxf(fmaf((va.x - mu) * rs, gv.x, bev.x), 0.f);
        float hy = fmaxf(fmaf((va.y - mu) * rs, gv.y, bev.y), 0.f);
        float hz = fmaxf(fmaf((vb2.x - mu) * rs, gv.z, bev.z), 0.f);
        float hw = fmaxf(fmaf((vb2.y - mu) * rs, gv.w, bev.w), 0.f);
        if (!FINAL) {
            u64 h0 = pk2(hx, hy), h1 = pk2(hz, hw);
#pragma unroll
            for (int k = 0; k < MODES; k++) { fma2(c0[k], up[k], h0); fma2(c1[k], up[k], h1); }
        } else {
            u64 r0 = 0ull, r1 = 0ull, r2 = 0ull, r3 = 0ull;
            u64 t;
            t = pks(hx); fma2(r0, t, wo[0][0]); fma2(r1, t, wo[0][1]);
                         fma2(r2, t, wo[0][2]); fma2(r3, t, wo[0][3]);
            t = pks(hy); fma2(r0, t, wo[1][0]); fma2(r1, t, wo[1][1]);
                         fma2(r2, t, wo[1][2]); fma2(r3, t, wo[1][3]);
            t = pks(hz); fma2(r0, t, wo[2][0]); fma2(r1, t, wo[2][1]);
                         fma2(r2, t, wo[2][2]); fma2(r3, t, wo[2][3]);
            t = pks(hw); fma2(r0, t, wo[3][0]); fma2(r1, t, wo[3][1]);
                         fma2(r2, t, wo[3][2]); fma2(r3, t, wo[3][3]);
            u64 red = hred8(r0, r1, r2, r3, lane);
            add2(red, bop);
            if ((lane & 7) == 0) {
                *(u64*)&outg[(size_t)g * (NNODE * FPN) + n * FPN + (lane >> 3) * 2] = red;
            }
        }
    }
    if (!FINAL) {
        if (nh == 0) {
#pragma unroll
            for (int k = 0; k < MODES; k++) {
                ulonglong2 r; r.x = c0[k]; r.y = c1[k];
                *(ulonglong2*)&S.B[g][k][jc] = r;
            }
        }
        __syncthreads();
        if (nh == 1) {
#pragma unroll
            for (int k = 0; k < MODES; k++) {
                ulonglong2 t = *(const ulonglong2*)&S.B[g][k][jc];
                add2(c0[k], t.x); add2(c1[k], t.y);
                ulonglong2 r; r.x = c0[k]; r.y = c1[k];
                *(ulonglong2*)&S.A[g][k][jc] = r;
            }
        }
        __syncthreads();
    }
}

// ---------------- main fused kernel ----------------
__global__ __launch_bounds__(NT, 1) void fused_kernel(
    const float* __restrict__ x, const float* __restrict__ U,
    const float* __restrict__ Wp, const float* __restrict__ bp,
    const float* __restrict__ bs1, const float* __restrict__ bn1,
    const float* __restrict__ g1, const float* __restrict__ be1,
    const float* __restrict__ bs3, const float* __restrict__ bn3,
    const float* __restrict__ g3, const float* __restrict__ be3,
    const float* __restrict__ Wo, const float* __restrict__ bo,
    float* __restrict__ out) {
    extern __shared__ __align__(16) float smem_raw[];
    Smem& S = *reinterpret_cast<Smem*>(smem_raw);
    const int tid  = threadIdx.x;
    const int lane = tid & 31;
    const int warp = tid >> 5;
    const int item0 = blockIdx.x * G;

    if (tid < NNODE * MODES) S.sU8[tid >> 3][tid & 7] = U[(tid >> 3) * NNODE + (tid & 7)];
    for (int o = tid; o < FPN * H; o += NT) { S.sWp[o] = Wp[o]; S.sWo[o] = Wo[o]; }
    if (tid < H) {
        S.bp[tid] = bp[tid];
        S.b1[tid] = bs1[tid] + bn1[tid];
        S.gm1[tid] = g1[tid]; S.be1[tid] = be1[tid];
        S.b3[tid] = bs3[tid] + bn3[tid];
        S.gm3[tid] = g3[tid]; S.be3[tid] = be3[tid];
    }
    if (tid < MODES) S.ss[tid] = g_s[tid];
    if (tid < FPN) S.sbo[tid] = bo[tid];
    {
        const float* xg = x + (size_t)item0 * (NNODE * FPN);
        for (int o = tid; o < G * NNODE * FPN; o += NT) S.sX[o] = xg[o];
    }
    __syncthreads();

    {
        int g = tid >> 6, k = (tid >> 3) & 7, f = tid & 7;
        float a = 0.f;
#pragma unroll 8
        for (int n = 0; n < NNODE; n++) a += S.sU8[n][k] * S.sX[g * 512 + n * FPN + f];
        S.sXS[g][k][f] = a;
    }
    __syncthreads();

    {
        const int g = warp >> 1, kh = (warp & 1) * 4, jc = lane * 4;
        const float4 bpv = *(const float4*)&S.bp[jc];
#pragma unroll
        for (int k = kh; k < kh + 4; k++) {
            const float sk = S.ss[k];
            float4 acc = make_float4(sk * bpv.x, sk * bpv.y, sk * bpv.z, sk * bpv.w);
#pragma unroll
            for (int f = 0; f < FPN; f++)
                fma4(acc, S.sXS[g][k][f], *(const float4*)&S.sWp[f * H + jc]);
            *(float4*)&S.A[g][k][jc] = acc;
        }
    }
    __syncthreads();

    mode_mix(S.A, S.B, g_w0h, warp, lane);
    __syncthreads();
    {
#pragma unroll
        for (int e = 0; e < 2; e++) {
            int o = tid + e * NT;
            int g = o >> 7, i = o & 127;
            float a = 0.f;
#pragma unroll
            for (int k = 0; k < MODES; k++) a += S.ss[k] * S.B[g][k][i];
            S.vbar[g][i] = a;
        }
    }
    __syncthreads();
    pq_gemm(S, g_Wa1h, g_Wb1h, warp, lane);
    __syncthreads();
    expand<false>(S, S.b1, S.gm1, S.be1, nullptr, warp, lane);

    mode_mix(S.A, S.B, g_w2h, warp, lane);
    __syncthreads();
    {
#pragma unroll
        for (int e = 0; e < 2; e++) {
            int o = tid + e * NT;
            int g = o >> 7, i = o & 127;
            float a = 0.f;
#pragma unroll
            for (int k = 0; k < MODES; k++) a += S.ss[k] * S.B[g][k][i];
            S.vbar[g][i] = a;
        }
    }
    __syncthreads();
    pq_gemm(S, g_Wa3h, g_Wb3h, warp, lane);
    __syncthreads();
    expand<true>(S, S.b3, S.gm3, S.be3, out + (size_t)item0 * (NNODE * FPN), warp, lane);
}

// ---------------- launch ----------------
extern "C" void kernel_launch(void* const* d_in, const int* in_sizes, int n_in,
                              void* d_out, int out_size) {
    const float* x   = (const float*)d_in[0];
    const float* adj = (const float*)d_in[1];
    const float* U   = (const float*)d_in[2];
    const float* Wp  = (const float*)d_in[3];
    const float* bp  = (const float*)d_in[4];
    const float* w0  = (const float*)d_in[5];
    const float* w2  = (const float*)d_in[6];
    const float* Ws1 = (const float*)d_in[7];
    const float* bs1 = (const float*)d_in[8];
    const float* Wn1 = (const float*)d_in[9];
    const float* bn1 = (const float*)d_in[10];
    const float* g1  = (const float*)d_in[11];
    const float* be1 = (const float*)d_in[12];
    const float* Ws3 = (const float*)d_in[13];
    const float* bs3 = (const float*)d_in[14];
    const float* Wn3 = (const float*)d_in[15];
    const float* bn3 = (const float*)d_in[16];
    const float* g3  = (const float*)d_in[17];
    const float* be3 = (const float*)d_in[18];
    const float* Wo  = (const float*)d_in[19];
    const float* bo  = (const float*)d_in[20];
    float* out = (float*)d_out;

    cudaFuncSetAttribute(fused_kernel, cudaFuncAttributeMaxDynamicSharedMemorySize,
                         (int)sizeof(Smem));
    prep_all<<<256, 256>>>(w0, w2, adj, U, Ws1, Wn1, Ws3, Wn3);
    fused_kernel<<<BT / G, NT, sizeof(Smem)>>>(
        x, U, Wp, bp, bs1, bn1, g1, be1,
        bs3, bn3, g3, be3, Wo, bo, out);
}

// round 12
// speedup vs baseline: 1.0613x; 1.0613x over previous
#include <cuda_runtime.h>
#include <cuda_fp16.h>

#define G      8
#define NNODE  64
#define FPN    8
#define H      128
#define MODES  8
#define BT     16384
#define NT     512

typedef unsigned long long u64;

__device__ __align__(16) __half g_w0h[MODES * H * H];  // [k][i][j] fp16
__device__ __align__(16) __half g_w2h[MODES * H * H];
__device__ __align__(16) __half g_Wa1h[H * H];         // Ws1 - invd*Wn1
__device__ __align__(16) __half g_Wb1h[H * H];         // invd*Wn1
__device__ __align__(16) __half g_Wa3h[H * H];
__device__ __align__(16) __half g_Wb3h[H * H];
__device__ float g_s[MODES];
__device__ float g_invd;

__device__ __forceinline__ u64 pks(float a) {
    u64 r; asm("mov.b64 %0,{%1,%1};" : "=l"(r) : "f"(a)); return r;
}
__device__ __forceinline__ u64 pk2(float a, float b) {
    u64 r; asm("mov.b64 %0,{%1,%2};" : "=l"(r) : "f"(a), "f"(b)); return r;
}
__device__ __forceinline__ void fma2(u64& d, u64 a, u64 b) {
    asm("fma.rn.f32x2 %0,%1,%2,%0;" : "+l"(d) : "l"(a), "l"(b));
}
__device__ __forceinline__ void add2(u64& d, u64 a) {
    asm("add.rn.f32x2 %0,%0,%1;" : "+l"(d) : "l"(a));
}
__device__ __forceinline__ float2 up2(u64 a) {
    float2 r; asm("mov.b64 {%0,%1},%2;" : "=f"(r.x), "=f"(r.y) : "l"(a)); return r;
}
__device__ __forceinline__ void fma4(float4& a, float s, const float4 b) {
    a.x = fmaf(s, b.x, a.x); a.y = fmaf(s, b.y, a.y);
    a.z = fmaf(s, b.z, a.z); a.w = fmaf(s, b.w, a.w);
}
__device__ __forceinline__ u64 ldw(const __half* p) {
    __half2 h = *(const __half2*)p;
    float2 f = __half22float2(h);
    return pk2(f.x, f.y);
}

// Hierarchically reduce 8 floats (4 u64 pairs) across the warp.
__device__ __forceinline__ u64 hred8(u64 r0, u64 r1, u64 r2, u64 r3, int lane) {
    u64 t0 = __shfl_xor_sync(0xffffffffu, r0, 16);
    u64 t1 = __shfl_xor_sync(0xffffffffu, r1, 16);
    u64 t2 = __shfl_xor_sync(0xffffffffu, r2, 16);
    u64 t3 = __shfl_xor_sync(0xffffffffu, r3, 16);
    u64 a0, a1;
    if (lane < 16) { a0 = r0; add2(a0, t0); a1 = r1; add2(a1, t1); }
    else           { a0 = r2; add2(a0, t2); a1 = r3; add2(a1, t3); }
    u64 s0 = __shfl_xor_sync(0xffffffffu, a0, 8);
    u64 s1 = __shfl_xor_sync(0xffffffffu, a1, 8);
    u64 b;
    if ((lane & 8) == 0) { b = a0; add2(b, s0); }
    else                 { b = a1; add2(b, s1); }
    u64 c;
    c = __shfl_xor_sync(0xffffffffu, b, 4); add2(b, c);
    c = __shfl_xor_sync(0xffffffffu, b, 2); add2(b, c);
    c = __shfl_xor_sync(0xffffffffu, b, 1); add2(b, c);
    return b;
}

struct Smem {
    float A[G][MODES][H];
    float B[G][MODES][H];
    float P[G][MODES][H];
    float vbar[G][H];
    float qbar[G][H];
    float sX[G * NNODE * FPN];
    float sXS[G][MODES][FPN];
    float sU8[NNODE][MODES];
    float sWp[FPN * H];
    float sWo[H * FPN];
    float bp[H];
    float b1[H]; float gm1[H]; float be1[H];
    float b3[H]; float gm3[H]; float be3[H];
    float ss[MODES]; float sbo[FPN];
    // live layer's pq weights (fp16, 64KB; re-staged between layers)
    __half hWa[H * H];
    __half hWb[H * H];
};

// ---------------- prep ----------------
__global__ void prep_all(const float* __restrict__ w0, const float* __restrict__ w2,
                         const float* __restrict__ adj, const float* __restrict__ Uin,
                         const float* __restrict__ Ws1, const float* __restrict__ Wn1,
                         const float* __restrict__ Ws3, const float* __restrict__ Wn3) {
    const float invd = adj[1];
    const int total = MODES * H * H;
    for (int o = blockIdx.x * blockDim.x + threadIdx.x; o < total;
         o += gridDim.x * blockDim.x) {
        int k = o >> 14, rem = o & 16383, i = rem >> 7, j = rem & 127;
        int src = ((i << 7) + j) * MODES + k;
        g_w0h[o] = __float2half(w0[src]);
        g_w2h[o] = __float2half(w2[src]);
    }
    for (int o = blockIdx.x * blockDim.x + threadIdx.x; o < H * H;
         o += gridDim.x * blockDim.x) {
        float wn1 = Wn1[o], wn3 = Wn3[o];
        g_Wa1h[o] = __float2half(Ws1[o] - invd * wn1);
        g_Wb1h[o] = __float2half(invd * wn1);
        g_Wa3h[o] = __float2half(Ws3[o] - invd * wn3);
        g_Wb3h[o] = __float2half(invd * wn3);
    }
    if (blockIdx.x == 0 && threadIdx.x < MODES) {
        int k = threadIdx.x;
        float s = 0.f;
        for (int m = 0; m < NNODE; m++) s += Uin[m * NNODE + k];
        g_s[k] = s;
        if (k == 0) g_invd = invd;
    }
}

// stage one layer's Wa/Wb into smem (coalesced uint4)
__device__ __forceinline__ void stage_w(Smem& S, const __half* __restrict__ Wa,
                                        const __half* __restrict__ Wb, int tid) {
    const uint4* sa = (const uint4*)Wa;
    const uint4* sb = (const uint4*)Wb;
    uint4* da = (uint4*)S.hWa;
    uint4* db = (uint4*)S.hWb;
#pragma unroll
    for (int t = 0; t < 4; t++) {
        int o = tid + t * NT;
        da[o] = sa[o];
        db[o] = sb[o];
    }
}

// ---------------- stages (16 warps) ----------------
__device__ __forceinline__ void mode_mix(const float (*xf)[MODES][H],
                                         float (*of)[MODES][H],
                                         const __half* __restrict__ wt,
                                         int warp, int lane) {
    const int k = warp >> 1;
    const int j2 = (warp & 1) * 64 + lane * 2;
    const __half* wk = wt + k * (H * H) + j2;
    u64 acc[G];
#pragma unroll
    for (int g = 0; g < G; g++) acc[g] = 0ull;
#pragma unroll 4
    for (int i4 = 0; i4 < H / 4; i4++) {
        float4 xv[G];
#pragma unroll
        for (int g = 0; g < G; g++) xv[g] = *(const float4*)&xf[g][k][i4 * 4];
        u64 w[4];
#pragma unroll
        for (int ii = 0; ii < 4; ii++) w[ii] = ldw(wk + (i4 * 4 + ii) * H);
#pragma unroll
        for (int ii = 0; ii < 4; ii++)
#pragma unroll
            for (int g = 0; g < G; g++) fma2(acc[g], pks((&xv[g].x)[ii]), w[ii]);
    }
#pragma unroll
    for (int g = 0; g < G; g++) *(u64*)&of[g][k][j2] = acc[g];
}

// P'[g,k,j] = of[g,k,:]@Wa ; qbar[g,j] = vbar[g,:]@Wb  — weights in SMEM
__device__ void pq_gemm(Smem& S, int warp, int lane) {
    const int g = warp >> 1;
    const int j2 = (warp & 1) * 64 + lane * 2;
    const __half* wa = S.hWa + j2;
    const __half* wb = S.hWb + j2;
    u64 acc[MODES];
    u64 accq = 0ull;
#pragma unroll
    for (int k = 0; k < MODES; k++) acc[k] = 0ull;
#pragma unroll 2
    for (int i4 = 0; i4 < H / 4; i4++) {
        float4 ov[MODES];
#pragma unroll
        for (int k = 0; k < MODES; k++)
            ov[k] = *(const float4*)&S.B[g][k][i4 * 4];
        float4 vv = *(const float4*)&S.vbar[g][i4 * 4];
        u64 wav[4], wbv[4];
#pragma unroll
        for (int ii = 0; ii < 4; ii++) {
            wav[ii] = ldw(wa + (i4 * 4 + ii) * H);
            wbv[ii] = ldw(wb + (i4 * 4 + ii) * H);
        }
#pragma unroll
        for (int ii = 0; ii < 4; ii++) {
#pragma unroll
            for (int k = 0; k < MODES; k++)
                fma2(acc[k], pks((&ov[k].x)[ii]), wav[ii]);
            fma2(accq, pks((&vv.x)[ii]), wbv[ii]);
        }
    }
#pragma unroll
    for (int k = 0; k < MODES; k++) *(u64*)&S.P[g][k][j2] = acc[k];
    *(u64*)&S.qbar[g][j2] = accq;
}

template <bool FINAL>
__device__ void expand(Smem& S, const float* __restrict__ bsum,
                       const float* __restrict__ gam, const float* __restrict__ bet,
                       float* __restrict__ outg, int warp, int lane) {
    const int g = warp >> 1;
    const int nh = warp & 1;
    const int jc = lane * 4;
    u64 pp0[MODES], pp1[MODES], c0[MODES], c1[MODES];
#pragma unroll
    for (int k = 0; k < MODES; k++) {
        ulonglong2 tp = *(const ulonglong2*)&S.P[g][k][jc];
        pp0[k] = tp.x; pp1[k] = tp.y;
        c0[k] = 0ull; c1[k] = 0ull;
    }
    const ulonglong2 bv = *(const ulonglong2*)&bsum[jc];
    const ulonglong2 qv = *(const ulonglong2*)&S.qbar[g][jc];
    u64 vb0 = bv.x; add2(vb0, qv.x);
    u64 vb1 = bv.y; add2(vb1, qv.y);

    float mb;
    {
        float2 e0 = up2(vb0), e1 = up2(vb1);
        mb = e0.x + e0.y + e1.x + e1.y;
#pragma unroll
        for (int off = 16; off > 0; off >>= 1)
            mb += __shfl_xor_sync(0xffffffffu, mb, off);
    }
    float SPf[8];
    {
        float spl[8];
#pragma unroll
        for (int k = 0; k < MODES; k++) {
            float2 e0 = up2(pp0[k]), e1 = up2(pp1[k]);
            spl[k] = e0.x + e0.y + e1.x + e1.y;
        }
        u64 red = hred8(pk2(spl[0], spl[1]), pk2(spl[2], spl[3]),
                        pk2(spl[4], spl[5]), pk2(spl[6], spl[7]), lane);
        float2 p01 = up2(__shfl_sync(0xffffffffu, red, 0));
        float2 p23 = up2(__shfl_sync(0xffffffffu, red, 8));
        float2 p45 = up2(__shfl_sync(0xffffffffu, red, 16));
        float2 p67 = up2(__shfl_sync(0xffffffffu, red, 24));
        SPf[0] = p01.x; SPf[1] = p01.y; SPf[2] = p23.x; SPf[3] = p23.y;
        SPf[4] = p45.x; SPf[5] = p45.y; SPf[6] = p67.x; SPf[7] = p67.y;
    }

    const float4 gv  = *(const float4*)&gam[jc];
    const float4 bev = *(const float4*)&bet[jc];
    u64 wo[4][4];
    u64 bop = 0ull;
    if (FINAL) {
#pragma unroll
        for (int c = 0; c < 4; c++) {
            ulonglong2 lo = *(const ulonglong2*)&S.sWo[(jc + c) * FPN];
            ulonglong2 hi = *(const ulonglong2*)&S.sWo[(jc + c) * FPN + 4];
            wo[c][0] = lo.x; wo[c][1] = lo.y; wo[c][2] = hi.x; wo[c][3] = hi.y;
        }
        bop = *(const u64*)&S.sbo[(lane >> 3) * 2];
    }
    const int n0 = nh * 32;
    for (int n = n0; n < n0 + 32; n++) {
        float4 u0 = *(const float4*)&S.sU8[n][0];
        float4 u1 = *(const float4*)&S.sU8[n][4];
        u64 up[MODES];
        up[0] = pks(u0.x); up[1] = pks(u0.y); up[2] = pks(u0.z); up[3] = pks(u0.w);
        up[4] = pks(u1.x); up[5] = pks(u1.y); up[6] = pks(u1.z); up[7] = pks(u1.w);
        u64 v0 = vb0, v1 = vb1;
#pragma unroll
        for (int k = 0; k < MODES; k++) { fma2(v0, up[k], pp0[k]); fma2(v1, up[k], pp1[k]); }
        float2 va = up2(v0), vb2 = up2(v1);
        float smv = mb;
        smv = fmaf(u0.x, SPf[0], smv); smv = fmaf(u0.y, SPf[1], smv);
        smv = fmaf(u0.z, SPf[2], smv); smv = fmaf(u0.w, SPf[3], smv);
        smv = fmaf(u1.x, SPf[4], smv); smv = fmaf(u1.y, SPf[5], smv);
        smv = fmaf(u1.z, SPf[6], smv); smv = fmaf(u1.w, SPf[7], smv);
        float sq = va.x * va.x + va.y * va.y + vb2.x * vb2.x + vb2.y * vb2.y;
#pragma unroll
        for (int off = 16; off > 0; off >>= 1)
            sq += __shfl_xor_sync(0xffffffffu, sq, off);
        const float mu  = smv * (1.0f / H);
        const float var = sq * (1.0f / H) - mu * mu;
        const float rs  = rsqrtf(var + 1e-5f);
        float hx = fmaxf(fmaf((va.x - mu) * rs, gv.x, bev.x), 0.f);
        float hy = fmaxf(fmaf((va.y - mu) * rs, gv.y, bev.y), 0.f);
        float hz = fmaxf(fmaf((vb2.x - mu) * rs, gv.z, bev.z), 0.f);
        float hw = fmaxf(fmaf((vb2.y - mu) * rs, gv.w, bev.w), 0.f);
        if (!FINAL) {
            u64 h0 = pk2(hx, hy), h1 = pk2(hz, hw);
#pragma unroll
            for (int k = 0; k < MODES; k++) { fma2(c0[k], up[k], h0); fma2(c1[k], up[k], h1); }
        } else {
            u64 r0 = 0ull, r1 = 0ull, r2 = 0ull, r3 = 0ull;
            u64 t;
            t = pks(hx); fma2(r0, t, wo[0][0]); fma2(r1, t, wo[0][1]);
                         fma2(r2, t, wo[0][2]); fma2(r3, t, wo[0][3]);
            t = pks(hy); fma2(r0, t, wo[1][0]); fma2(r1, t, wo[1][1]);
                         fma2(r2, t, wo[1][2]); fma2(r3, t, wo[1][3]);
            t = pks(hz); fma2(r0, t, wo[2][0]); fma2(r1, t, wo[2][1]);
                         fma2(r2, t, wo[2][2]); fma2(r3, t, wo[2][3]);
            t = pks(hw); fma2(r0, t, wo[3][0]); fma2(r1, t, wo[3][1]);
                         fma2(r2, t, wo[3][2]); fma2(r3, t, wo[3][3]);
            u64 red = hred8(r0, r1, r2, r3, lane);
            add2(red, bop);
            if ((lane & 7) == 0) {
                *(u64*)&outg[(size_t)g * (NNODE * FPN) + n * FPN + (lane >> 3) * 2] = red;
            }
        }
    }
    if (!FINAL) {
        if (nh == 0) {
#pragma unroll
            for (int k = 0; k < MODES; k++) {
                ulonglong2 r; r.x = c0[k]; r.y = c1[k];
                *(ulonglong2*)&S.B[g][k][jc] = r;
            }
        }
        __syncthreads();
        if (nh == 1) {
#pragma unroll
            for (int k = 0; k < MODES; k++) {
                ulonglong2 t = *(const ulonglong2*)&S.B[g][k][jc];
                add2(c0[k], t.x); add2(c1[k], t.y);
                ulonglong2 r; r.x = c0[k]; r.y = c1[k];
                *(ulonglong2*)&S.A[g][k][jc] = r;
            }
        }
        __syncthreads();
    }
}

// ---------------- main fused kernel ----------------
__global__ __launch_bounds__(NT, 1) void fused_kernel(
    const float* __restrict__ x, const float* __restrict__ U,
    const float* __restrict__ Wp, const float* __restrict__ bp,
    const float* __restrict__ bs1, const float* __restrict__ bn1,
    const float* __restrict__ g1, const float* __restrict__ be1,
    const float* __restrict__ bs3, const float* __restrict__ bn3,
    const float* __restrict__ g3, const float* __restrict__ be3,
    const float* __restrict__ Wo, const float* __restrict__ bo,
    float* __restrict__ out) {
    extern __shared__ __align__(16) float smem_raw[];
    Smem& S = *reinterpret_cast<Smem*>(smem_raw);
    const int tid  = threadIdx.x;
    const int lane = tid & 31;
    const int warp = tid >> 5;
    const int item0 = blockIdx.x * G;

    // prologue: constants + x + layer-1 pq weights (fp16, 64KB into smem)
    if (tid < NNODE * MODES) S.sU8[tid >> 3][tid & 7] = U[(tid >> 3) * NNODE + (tid & 7)];
    for (int o = tid; o < FPN * H; o += NT) { S.sWp[o] = Wp[o]; S.sWo[o] = Wo[o]; }
    if (tid < H) {
        S.bp[tid] = bp[tid];
        S.b1[tid] = bs1[tid] + bn1[tid];
        S.gm1[tid] = g1[tid]; S.be1[tid] = be1[tid];
        S.b3[tid] = bs3[tid] + bn3[tid];
        S.gm3[tid] = g3[tid]; S.be3[tid] = be3[tid];
    }
    if (tid < MODES) S.ss[tid] = g_s[tid];
    if (tid < FPN) S.sbo[tid] = bo[tid];
    {
        const float* xg = x + (size_t)item0 * (NNODE * FPN);
        for (int o = tid; o < G * NNODE * FPN; o += NT) S.sX[o] = xg[o];
    }
    stage_w(S, g_Wa1h, g_Wb1h, tid);
    __syncthreads();

    // xs[g,k,f] = sum_n U8[n,k]*x[g,n,f]
    {
        int g = tid >> 6, k = (tid >> 3) & 7, f = tid & 7;
        float a = 0.f;
#pragma unroll 8
        for (int n = 0; n < NNODE; n++) a += S.sU8[n][k] * S.sX[g * 512 + n * FPN + f];
        S.sXS[g][k][f] = a;
    }
    __syncthreads();

    // xf0 = xs@Wp + s*bp   (warp=(g, k-half))
    {
        const int g = warp >> 1, kh = (warp & 1) * 4, jc = lane * 4;
        const float4 bpv = *(const float4*)&S.bp[jc];
#pragma unroll
        for (int k = kh; k < kh + 4; k++) {
            const float sk = S.ss[k];
            float4 acc = make_float4(sk * bpv.x, sk * bpv.y, sk * bpv.z, sk * bpv.w);
#pragma unroll
            for (int f = 0; f < FPN; f++)
                fma4(acc, S.sXS[g][k][f], *(const float4*)&S.sWp[f * H + jc]);
            *(float4*)&S.A[g][k][jc] = acc;
        }
    }
    __syncthreads();

    // ===== layer 0 + 1 =====
    mode_mix(S.A, S.B, g_w0h, warp, lane);
    __syncthreads();
    {
#pragma unroll
        for (int e = 0; e < 2; e++) {
            int o = tid + e * NT;
            int g = o >> 7, i = o & 127;
            float a = 0.f;
#pragma unroll
            for (int k = 0; k < MODES; k++) a += S.ss[k] * S.B[g][k][i];
            S.vbar[g][i] = a;
        }
    }
    __syncthreads();
    pq_gemm(S, warp, lane);
    __syncthreads();
    expand<false>(S, S.b1, S.gm1, S.be1, nullptr, warp, lane);

    // ===== layer 2 + 3 =====
    mode_mix(S.A, S.B, g_w2h, warp, lane);
    // re-stage layer-3 pq weights; latency hides behind mode_mix/vbar work,
    // consumed only after the next __syncthreads
    stage_w(S, g_Wa3h, g_Wb3h, tid);
    __syncthreads();
    {
#pragma unroll
        for (int e = 0; e < 2; e++) {
            int o = tid + e * NT;
            int g = o >> 7, i = o & 127;
            float a = 0.f;
#pragma unroll
            for (int k = 0; k < MODES; k++) a += S.ss[k] * S.B[g][k][i];
            S.vbar[g][i] = a;
        }
    }
    __syncthreads();
    pq_gemm(S, warp, lane);
    __syncthreads();
    expand<true>(S, S.b3, S.gm3, S.be3, out + (size_t)item0 * (NNODE * FPN), warp, lane);
}

// ---------------- launch ----------------
extern "C" void kernel_launch(void* const* d_in, const int* in_sizes, int n_in,
                              void* d_out, int out_size) {
    const float* x   = (const float*)d_in[0];
    const float* adj = (const float*)d_in[1];
    const float* U   = (const float*)d_in[2];
    const float* Wp  = (const float*)d_in[3];
    const float* bp  = (const float*)d_in[4];
    const float* w0  = (const float*)d_in[5];
    const float* w2  = (const float*)d_in[6];
    const float* Ws1 = (const float*)d_in[7];
    const float* bs1 = (const float*)d_in[8];
    const float* Wn1 = (const float*)d_in[9];
    const float* bn1 = (const float*)d_in[10];
    const float* g1  = (const float*)d_in[11];
    const float* be1 = (const float*)d_in[12];
    const float* Ws3 = (const float*)d_in[13];
    const float* bs3 = (const float*)d_in[14];
    const float* Wn3 = (const float*)d_in[15];
    const float* bn3 = (const float*)d_in[16];
    const float* g3  = (const float*)d_in[17];
    const float* be3 = (const float*)d_in[18];
    const float* Wo  = (const float*)d_in[19];
    const float* bo  = (const float*)d_in[20];
    float* out = (float*)d_out;

    cudaFuncSetAttribute(fused_kernel, cudaFuncAttributeMaxDynamicSharedMemorySize,
                         (int)sizeof(Smem));
    prep_all<<<256, 256>>>(w0, w2, adj, U, Ws1, Wn1, Ws3, Wn3);
    fused_kernel<<<BT / G, NT, sizeof(Smem)>>>(
        x, U, Wp, bp, bs1, bn1, g1, be1,
        bs3, bn3, g3, be3, Wo, bo, out);
}

// round 13
// speedup vs baseline: 1.1447x; 1.0786x over previous
#include <cuda_runtime.h>
#include <cuda_fp16.h>

#define G      8
#define NNODE  64
#define FPN    8
#define H      128
#define MODES  8
#define BT     16384
#define NT     512

typedef unsigned long long u64;

// combined weights: WP_k = W_k @ (Ws - invd*Wn);  WQ_k = s_k * W_k @ (invd*Wn)
__device__ __align__(16) __half g_WP0[MODES * H * H];  // layer0->1, [k][i][j]
__device__ __align__(16) __half g_WQ0[MODES * H * H];
__device__ __align__(16) __half g_WP2[MODES * H * H];  // layer2->3
__device__ __align__(16) __half g_WQ2[MODES * H * H];
__device__ float g_s[MODES];

__device__ __forceinline__ u64 pks(float a) {
    u64 r; asm("mov.b64 %0,{%1,%1};" : "=l"(r) : "f"(a)); return r;
}
__device__ __forceinline__ u64 pk2(float a, float b) {
    u64 r; asm("mov.b64 %0,{%1,%2};" : "=l"(r) : "f"(a), "f"(b)); return r;
}
__device__ __forceinline__ void fma2(u64& d, u64 a, u64 b) {
    asm("fma.rn.f32x2 %0,%1,%2,%0;" : "+l"(d) : "l"(a), "l"(b));
}
__device__ __forceinline__ void add2(u64& d, u64 a) {
    asm("add.rn.f32x2 %0,%0,%1;" : "+l"(d) : "l"(a));
}
__device__ __forceinline__ float2 up2(u64 a) {
    float2 r; asm("mov.b64 {%0,%1},%2;" : "=f"(r.x), "=f"(r.y) : "l"(a)); return r;
}
__device__ __forceinline__ void fma4(float4& a, float s, const float4 b) {
    a.x = fmaf(s, b.x, a.x); a.y = fmaf(s, b.y, a.y);
    a.z = fmaf(s, b.z, a.z); a.w = fmaf(s, b.w, a.w);
}
__device__ __forceinline__ u64 ldw(const __half* p) {
    __half2 h = *(const __half2*)p;
    float2 f = __half22float2(h);
    return pk2(f.x, f.y);
}

// Hierarchically reduce 8 floats (4 u64 pairs) across the warp.
__device__ __forceinline__ u64 hred8(u64 r0, u64 r1, u64 r2, u64 r3, int lane) {
    u64 t0 = __shfl_xor_sync(0xffffffffu, r0, 16);
    u64 t1 = __shfl_xor_sync(0xffffffffu, r1, 16);
    u64 t2 = __shfl_xor_sync(0xffffffffu, r2, 16);
    u64 t3 = __shfl_xor_sync(0xffffffffu, r3, 16);
    u64 a0, a1;
    if (lane < 16) { a0 = r0; add2(a0, t0); a1 = r1; add2(a1, t1); }
    else           { a0 = r2; add2(a0, t2); a1 = r3; add2(a1, t3); }
    u64 s0 = __shfl_xor_sync(0xffffffffu, a0, 8);
    u64 s1 = __shfl_xor_sync(0xffffffffu, a1, 8);
    u64 b;
    if ((lane & 8) == 0) { b = a0; add2(b, s0); }
    else                 { b = a1; add2(b, s1); }
    u64 c;
    c = __shfl_xor_sync(0xffffffffu, b, 4); add2(b, c);
    c = __shfl_xor_sync(0xffffffffu, b, 2); add2(b, c);
    c = __shfl_xor_sync(0xffffffffu, b, 1); add2(b, c);
    return b;
}

struct Smem {
    float A[G][MODES][H];   // xf
    float B[G][MODES][H];   // Q-partials (T), then expand scratch
    float P[G][MODES][H];   // P'
    float qbar[G][H];
    float sX[G * NNODE * FPN];
    float sXS[G][MODES][FPN];
    float sU8[NNODE][MODES];
    float sWp[FPN * H];
    float sWo[H * FPN];
    float bp[H];
    float b1[H]; float gm1[H]; float be1[H];
    float b3[H]; float gm3[H]; float be3[H];
    float ss[MODES]; float sbo[FPN];
};

// ---------------- prep: build combined weights ----------------
// grid = 64 blocks (layer(2) x k(8) x jchunk(4x32)), 256 threads
#define PREP_JC 32
__global__ void prep_combine(const float* __restrict__ w0, const float* __restrict__ w2,
                             const float* __restrict__ adj, const float* __restrict__ Uin,
                             const float* __restrict__ Ws1, const float* __restrict__ Wn1,
                             const float* __restrict__ Ws3, const float* __restrict__ Wn3) {
    extern __shared__ float ps[];          // wk[16384] + wa[4096] + wb[4096]
    float* wk = ps;
    float* wa = ps + 16384;
    float* wb = ps + 16384 + 4096;
    const int b = blockIdx.x;
    const int layer = b >> 5;
    const int k = (b >> 2) & 7;
    const int jc = (b & 3) * PREP_JC;
    const float* __restrict__ w  = layer ? w2  : w0;
    const float* __restrict__ Ws = layer ? Ws3 : Ws1;
    const float* __restrict__ Wn = layer ? Wn3 : Wn1;
    __half* WP = layer ? g_WP2 : g_WP0;
    __half* WQ = layer ? g_WQ2 : g_WQ0;
    const float invd = adj[1];
    const int tid = threadIdx.x;

    // s_k (column sum of U's first 8 cols)
    float sk = 0.f;
    for (int m = 0; m < NNODE; m++) sk += Uin[m * NNODE + k];

    // stage W_k[i][m] = w[(i*H+m)*MODES + k]
    for (int o = tid; o < H * H; o += 256) wk[o] = w[o * MODES + k];
    // stage Wa/Wb chunk [m][jc..jc+31]
    for (int o = tid; o < H * PREP_JC; o += 256) {
        int m = o / PREP_JC, j = jc + (o % PREP_JC);
        float wn = Wn[m * H + j];
        wa[o] = Ws[m * H + j] - invd * wn;
        wb[o] = invd * wn;
    }
    __syncthreads();

    const int i = tid >> 1;
    const int jh = (tid & 1) * 16;
    float accp[16], accq[16];
#pragma unroll
    for (int j = 0; j < 16; j++) { accp[j] = 0.f; accq[j] = 0.f; }
    for (int m = 0; m < H; m++) {
        float wv = wk[i * H + m];
#pragma unroll
        for (int j = 0; j < 16; j++) {
            accp[j] = fmaf(wv, wa[m * PREP_JC + jh + j], accp[j]);
            accq[j] = fmaf(wv, wb[m * PREP_JC + jh + j], accq[j]);
        }
    }
#pragma unroll
    for (int j = 0; j < 16; j++) {
        int col = jc + jh + j;
        WP[k * (H * H) + i * H + col] = __float2half(accp[j]);
        WQ[k * (H * H) + i * H + col] = __float2half(sk * accq[j]);
    }
    if (b == 0 && tid < MODES) {
        float s = 0.f;
        for (int m = 0; m < NNODE; m++) s += Uin[m * NNODE + tid];
        g_s[tid] = s;
    }
}

// ---------------- stages (16 warps) ----------------
// out[g,k,j] = sum_i xf[g,k,i]*wt[k][i][j]; warp=(k, j-half)
__device__ __forceinline__ void mode_mix(const float (*xf)[MODES][H],
                                         float (*of)[MODES][H],
                                         const __half* __restrict__ wt,
                                         int warp, int lane) {
    const int k = warp >> 1;
    const int j2 = (warp & 1) * 64 + lane * 2;
    const __half* wk = wt + k * (H * H) + j2;
    u64 acc[G];
#pragma unroll
    for (int g = 0; g < G; g++) acc[g] = 0ull;
#pragma unroll 4
    for (int i4 = 0; i4 < H / 4; i4++) {
        float4 xv[G];
#pragma unroll
        for (int g = 0; g < G; g++) xv[g] = *(const float4*)&xf[g][k][i4 * 4];
        u64 w[4];
#pragma unroll
        for (int ii = 0; ii < 4; ii++) w[ii] = ldw(wk + (i4 * 4 + ii) * H);
#pragma unroll
        for (int ii = 0; ii < 4; ii++)
#pragma unroll
            for (int g = 0; g < G; g++) fma2(acc[g], pks((&xv[g].x)[ii]), w[ii]);
    }
#pragma unroll
    for (int g = 0; g < G; g++) *(u64*)&of[g][k][j2] = acc[g];
}

// expand: v[n] = b + qbar + sum_k U8[n,k]*P'[k]; LN; ReLU; then
// MID: xf_next = U8^T h (2-warp combine) | FINAL: out = h@Wo + bo
template <bool FINAL>
__device__ void expand(Smem& S, const float* __restrict__ bsum,
                       const float* __restrict__ gam, const float* __restrict__ bet,
                       float* __restrict__ outg, int warp, int lane) {
    const int g = warp >> 1;
    const int nh = warp & 1;
    const int jc = lane * 4;
    u64 pp0[MODES], pp1[MODES], c0[MODES], c1[MODES];
#pragma unroll
    for (int k = 0; k < MODES; k++) {
        ulonglong2 tp = *(const ulonglong2*)&S.P[g][k][jc];
        pp0[k] = tp.x; pp1[k] = tp.y;
        c0[k] = 0ull; c1[k] = 0ull;
    }
    const ulonglong2 bv = *(const ulonglong2*)&bsum[jc];
    const ulonglong2 qv = *(const ulonglong2*)&S.qbar[g][jc];
    u64 vb0 = bv.x; add2(vb0, qv.x);
    u64 vb1 = bv.y; add2(vb1, qv.y);

    float mb;
    {
        float2 e0 = up2(vb0), e1 = up2(vb1);
        mb = e0.x + e0.y + e1.x + e1.y;
#pragma unroll
        for (int off = 16; off > 0; off >>= 1)
            mb += __shfl_xor_sync(0xffffffffu, mb, off);
    }
    float SPf[8];
    {
        float spl[8];
#pragma unroll
        for (int k = 0; k < MODES; k++) {
            float2 e0 = up2(pp0[k]), e1 = up2(pp1[k]);
            spl[k] = e0.x + e0.y + e1.x + e1.y;
        }
        u64 red = hred8(pk2(spl[0], spl[1]), pk2(spl[2], spl[3]),
                        pk2(spl[4], spl[5]), pk2(spl[6], spl[7]), lane);
        float2 p01 = up2(__shfl_sync(0xffffffffu, red, 0));
        float2 p23 = up2(__shfl_sync(0xffffffffu, red, 8));
        float2 p45 = up2(__shfl_sync(0xffffffffu, red, 16));
        float2 p67 = up2(__shfl_sync(0xffffffffu, red, 24));
        SPf[0] = p01.x; SPf[1] = p01.y; SPf[2] = p23.x; SPf[3] = p23.y;
        SPf[4] = p45.x; SPf[5] = p45.y; SPf[6] = p67.x; SPf[7] = p67.y;
    }

    const float4 gv  = *(const float4*)&gam[jc];
    const float4 bev = *(const float4*)&bet[jc];
    u64 wo[4][4];
    u64 bop = 0ull;
    if (FINAL) {
#pragma unroll
        for (int c = 0; c < 4; c++) {
            ulonglong2 lo = *(const ulonglong2*)&S.sWo[(jc + c) * FPN];
            ulonglong2 hi = *(const ulonglong2*)&S.sWo[(jc + c) * FPN + 4];
            wo[c][0] = lo.x; wo[c][1] = lo.y; wo[c][2] = hi.x; wo[c][3] = hi.y;
        }
        bop = *(const u64*)&S.sbo[(lane >> 3) * 2];
    }
    const int n0 = nh * 32;
    for (int n = n0; n < n0 + 32; n++) {
        float4 u0 = *(const float4*)&S.sU8[n][0];
        float4 u1 = *(const float4*)&S.sU8[n][4];
        u64 up[MODES];
        up[0] = pks(u0.x); up[1] = pks(u0.y); up[2] = pks(u0.z); up[3] = pks(u0.w);
        up[4] = pks(u1.x); up[5] = pks(u1.y); up[6] = pks(u1.z); up[7] = pks(u1.w);
        u64 v0 = vb0, v1 = vb1;
#pragma unroll
        for (int k = 0; k < MODES; k++) { fma2(v0, up[k], pp0[k]); fma2(v1, up[k], pp1[k]); }
        float2 va = up2(v0), vb2 = up2(v1);
        float smv = mb;
        smv = fmaf(u0.x, SPf[0], smv); smv = fmaf(u0.y, SPf[1], smv);
        smv = fmaf(u0.z, SPf[2], smv); smv = fmaf(u0.w, SPf[3], smv);
        smv = fmaf(u1.x, SPf[4], smv); smv = fmaf(u1.y, SPf[5], smv);
        smv = fmaf(u1.z, SPf[6], smv); smv = fmaf(u1.w, SPf[7], smv);
        float sq = va.x * va.x + va.y * va.y + vb2.x * vb2.x + vb2.y * vb2.y;
#pragma unroll
        for (int off = 16; off > 0; off >>= 1)
            sq += __shfl_xor_sync(0xffffffffu, sq, off);
        const float mu  = smv * (1.0f / H);
        const float var = sq * (1.0f / H) - mu * mu;
        const float rs  = rsqrtf(var + 1e-5f);
        float hx = fmaxf(fmaf((va.x - mu) * rs, gv.x, bev.x), 0.f);
        float hy = fmaxf(fmaf((va.y - mu) * rs, gv.y, bev.y), 0.f);
        float hz = fmaxf(fmaf((vb2.x - mu) * rs, gv.z, bev.z), 0.f);
        float hw = fmaxf(fmaf((vb2.y - mu) * rs, gv.w, bev.w), 0.f);
        if (!FINAL) {
            u64 h0 = pk2(hx, hy), h1 = pk2(hz, hw);
#pragma unroll
            for (int k = 0; k < MODES; k++) { fma2(c0[k], up[k], h0); fma2(c1[k], up[k], h1); }
        } else {
            u64 r0 = 0ull, r1 = 0ull, r2 = 0ull, r3 = 0ull;
            u64 t;
            t = pks(hx); fma2(r0, t, wo[0][0]); fma2(r1, t, wo[0][1]);
                         fma2(r2, t, wo[0][2]); fma2(r3, t, wo[0][3]);
            t = pks(hy); fma2(r0, t, wo[1][0]); fma2(r1, t, wo[1][1]);
                         fma2(r2, t, wo[1][2]); fma2(r3, t, wo[1][3]);
            t = pks(hz); fma2(r0, t, wo[2][0]); fma2(r1, t, wo[2][1]);
                         fma2(r2, t, wo[2][2]); fma2(r3, t, wo[2][3]);
            t = pks(hw); fma2(r0, t, wo[3][0]); fma2(r1, t, wo[3][1]);
                         fma2(r2, t, wo[3][2]); fma2(r3, t, wo[3][3]);
            u64 red = hred8(r0, r1, r2, r3, lane);
            add2(red, bop);
            if ((lane & 7) == 0) {
                *(u64*)&outg[(size_t)g * (NNODE * FPN) + n * FPN + (lane >> 3) * 2] = red;
            }
        }
    }
    if (!FINAL) {
        if (nh == 0) {
#pragma unroll
            for (int k = 0; k < MODES; k++) {
                ulonglong2 r; r.x = c0[k]; r.y = c1[k];
                *(ulonglong2*)&S.B[g][k][jc] = r;
            }
        }
        __syncthreads();
        if (nh == 1) {
#pragma unroll
            for (int k = 0; k < MODES; k++) {
                ulonglong2 t = *(const ulonglong2*)&S.B[g][k][jc];
                add2(c0[k], t.x); add2(c1[k], t.y);
                ulonglong2 r; r.x = c0[k]; r.y = c1[k];
                *(ulonglong2*)&S.A[g][k][jc] = r;
            }
        }
        __syncthreads();
    }
}

// ---------------- main fused kernel ----------------
__global__ __launch_bounds__(NT, 1) void fused_kernel(
    const float* __restrict__ x, const float* __restrict__ U,
    const float* __restrict__ Wp, const float* __restrict__ bp,
    const float* __restrict__ bs1, const float* __restrict__ bn1,
    const float* __restrict__ g1, const float* __restrict__ be1,
    const float* __restrict__ bs3, const float* __restrict__ bn3,
    const float* __restrict__ g3, const float* __restrict__ be3,
    const float* __restrict__ Wo, const float* __restrict__ bo,
    float* __restrict__ out) {
    extern __shared__ __align__(16) float smem_raw[];
    Smem& S = *reinterpret_cast<Smem*>(smem_raw);
    const int tid  = threadIdx.x;
    const int lane = tid & 31;
    const int warp = tid >> 5;
    const int item0 = blockIdx.x * G;

    // prologue
    if (tid < NNODE * MODES) S.sU8[tid >> 3][tid & 7] = U[(tid >> 3) * NNODE + (tid & 7)];
    for (int o = tid; o < FPN * H; o += NT) { S.sWp[o] = Wp[o]; S.sWo[o] = Wo[o]; }
    if (tid < H) {
        S.bp[tid] = bp[tid];
        S.b1[tid] = bs1[tid] + bn1[tid];
        S.gm1[tid] = g1[tid]; S.be1[tid] = be1[tid];
        S.b3[tid] = bs3[tid] + bn3[tid];
        S.gm3[tid] = g3[tid]; S.be3[tid] = be3[tid];
    }
    if (tid < MODES) S.ss[tid] = g_s[tid];
    if (tid < FPN) S.sbo[tid] = bo[tid];
    {
        const float* xg = x + (size_t)item0 * (NNODE * FPN);
        for (int o = tid; o < G * NNODE * FPN; o += NT) S.sX[o] = xg[o];
    }
    __syncthreads();

    // xs[g,k,f] = sum_n U8[n,k]*x[g,n,f]
    {
        int g = tid >> 6, k = (tid >> 3) & 7, f = tid & 7;
        float a = 0.f;
#pragma unroll 8
        for (int n = 0; n < NNODE; n++) a += S.sU8[n][k] * S.sX[g * 512 + n * FPN + f];
        S.sXS[g][k][f] = a;
    }
    __syncthreads();

    // xf0 = xs@Wp + s*bp   (warp=(g, k-half))
    {
        const int g = warp >> 1, kh = (warp & 1) * 4, jc = lane * 4;
        const float4 bpv = *(const float4*)&S.bp[jc];
#pragma unroll
        for (int k = kh; k < kh + 4; k++) {
            const float sk = S.ss[k];
            float4 acc = make_float4(sk * bpv.x, sk * bpv.y, sk * bpv.z, sk * bpv.w);
#pragma unroll
            for (int f = 0; f < FPN; f++)
                fma4(acc, S.sXS[g][k][f], *(const float4*)&S.sWp[f * H + jc]);
            *(float4*)&S.A[g][k][jc] = acc;
        }
    }
    __syncthreads();

    // ===== layers 0+1: P' = xf@WP0 ; T = xf@WQ0 ; qbar = sum_k T =====
    mode_mix(S.A, S.P, g_WP0, warp, lane);
    mode_mix(S.A, S.B, g_WQ0, warp, lane);
    __syncthreads();
    {
#pragma unroll
        for (int e = 0; e < 2; e++) {
            int o = tid + e * NT;
            int g = o >> 7, i = o & 127;
            float a = 0.f;
#pragma unroll
            for (int k = 0; k < MODES; k++) a += S.B[g][k][i];
            S.qbar[g][i] = a;
        }
    }
    __syncthreads();
    expand<false>(S, S.b1, S.gm1, S.be1, nullptr, warp, lane);

    // ===== layers 2+3 =====
    mode_mix(S.A, S.P, g_WP2, warp, lane);
    mode_mix(S.A, S.B, g_WQ2, warp, lane);
    __syncthreads();
    {
#pragma unroll
        for (int e = 0; e < 2; e++) {
            int o = tid + e * NT;
            int g = o >> 7, i = o & 127;
            float a = 0.f;
#pragma unroll
            for (int k = 0; k < MODES; k++) a += S.B[g][k][i];
            S.qbar[g][i] = a;
        }
    }
    __syncthreads();
    expand<true>(S, S.b3, S.gm3, S.be3, out + (size_t)item0 * (NNODE * FPN), warp, lane);
}

// ---------------- launch ----------------
extern "C" void kernel_launch(void* const* d_in, const int* in_sizes, int n_in,
                              void* d_out, int out_size) {
    const float* x   = (const float*)d_in[0];
    const float* adj = (const float*)d_in[1];
    const float* U   = (const float*)d_in[2];
    const float* Wp  = (const float*)d_in[3];
    const float* bp  = (const float*)d_in[4];
    const float* w0  = (const float*)d_in[5];
    const float* w2  = (const float*)d_in[6];
    const float* Ws1 = (const float*)d_in[7];
    const float* bs1 = (const float*)d_in[8];
    const float* Wn1 = (const float*)d_in[9];
    const float* bn1 = (const float*)d_in[10];
    const float* g1  = (const float*)d_in[11];
    const float* be1 = (const float*)d_in[12];
    const float* Ws3 = (const float*)d_in[13];
    const float* bs3 = (const float*)d_in[14];
    const float* Wn3 = (const float*)d_in[15];
    const float* bn3 = (const float*)d_in[16];
    const float* g3  = (const float*)d_in[17];
    const float* be3 = (const float*)d_in[18];
    const float* Wo  = (const float*)d_in[19];
    const float* bo  = (const float*)d_in[20];
    float* out = (float*)d_out;

    const int prep_smem = (16384 + 4096 + 4096) * (int)sizeof(float);  // 96KB
    cudaFuncSetAttribute(prep_combine, cudaFuncAttributeMaxDynamicSharedMemorySize,
                         prep_smem);
    cudaFuncSetAttribute(fused_kernel, cudaFuncAttributeMaxDynamicSharedMemorySize,
                         (int)sizeof(Smem));

    prep_combine<<<64, 256, prep_smem>>>(w0, w2, adj, U, Ws1, Wn1, Ws3, Wn3);
    fused_kernel<<<BT / G, NT, sizeof(Smem)>>>(
        x, U, Wp, bp, bs1, bn1, g1, be1,
        bs3, bn3, g3, be3, Wo, bo, out);
}